// round 12
// baseline (speedup 1.0000x reference)
#include <cuda_runtime.h>
#include <cstdint>

#define NN 16384
#define MM 2048
#define DD 256

// 64-row n-tiles, 256 CTAs, 2 CTAs/SM, 288 threads (8 consumer warps + 1 producer).
// dynamic SMEM layout (bytes)
#define SM_A     0                 // A': 4096 uint4 = 65536
#define SM_B     65536             // 4 stages x 512 uint4 (8KB) = 32768
#define SM_ZPART 98304             // 256 f32
#define SM_ZROW  99328             // 64 f32
#define SM_MBAR  99584             // full[4] @ +0..31, empty[4] @ +32..63
#define SMEM_TOTAL 99712

__device__ __align__(16) float g_eB[DD * MM];   // fragment-packed B (tf32)
__device__ float    g_esq[MM];
__device__ unsigned g_colmin[MM];

// ---------------------------------------------------------------------------
__device__ __forceinline__ float to_tf32(float x) {
    float y; asm("cvt.rna.tf32.f32 %0, %1;" : "=f"(y) : "f"(x)); return y;
}
__device__ __forceinline__ uint32_t smem_u32(const void* p) {
    uint32_t a;
    asm("{ .reg .u64 t; cvta.to.shared.u64 t, %1; cvt.u32.u64 %0, t; }" : "=r"(a) : "l"(p));
    return a;
}
__device__ __forceinline__ uint32_t elect_one_pred() {
    uint32_t pred;
    asm volatile("{\n\t.reg .pred p;\n\telect.sync _|p, 0xFFFFFFFF;\n\t"
                 "selp.b32 %0, 1, 0, p;\n\t}" : "=r"(pred));
    return pred;
}
#define CP_ASYNC16(dst, src) \
    asm volatile("cp.async.cg.shared.global [%0], [%1], 16;" :: "r"(dst), "l"(src))
#define CP_COMMIT() asm volatile("cp.async.commit_group;" ::: "memory")
#define CP_WAIT(n)  asm volatile("cp.async.wait_group %0;" :: "n"(n) : "memory")
#define RED_MIN_U32(ptr, val) \
    asm volatile("red.global.min.u32 [%0], %1;" :: "l"(ptr), "r"(val) : "memory")
#define MBAR_INIT(mb, c)  asm volatile("mbarrier.init.shared.b64 [%0], %1;" :: "r"((uint32_t)(mb)), "r"((uint32_t)(c)) : "memory")
#define MBAR_ARRIVE(mb)   asm volatile("mbarrier.arrive.shared.b64 _, [%0];" :: "r"((uint32_t)(mb)) : "memory")

#define MBAR_WAIT(mb, par) do { \
    uint32_t _m = (uint32_t)(mb), _p = (uint32_t)(par), _d; \
    asm volatile("{\n\t.reg .pred p;\n\t" \
        "mbarrier.try_wait.parity.acquire.cta.shared::cta.b64 p, [%1], %2;\n\t" \
        "selp.b32 %0, 1, 0, p;\n\t}" : "=r"(_d) : "r"(_m), "r"(_p) : "memory"); \
    if (!_d) { \
        asm volatile("{\n\t.reg .pred P1;\n\t" \
            "WL_%=:\n\t" \
            "mbarrier.try_wait.parity.acquire.cta.shared::cta.b64 P1, [%0], %1, 0x989680;\n\t" \
            "@P1 bra.uni WD_%=;\n\tbra.uni WL_%=;\n\tWD_%=:\n\t}" \
            :: "r"(_m), "r"(_p) : "memory"); \
    } \
} while (0)

__device__ __forceinline__ void mma_tf32(float4& d, const uint4& a, uint32_t b0, uint32_t b1) {
    asm volatile("mma.sync.aligned.m16n8k8.row.col.f32.tf32.tf32.f32 "
        "{%0,%1,%2,%3}, {%4,%5,%6,%7}, {%8,%9}, {%0,%1,%2,%3};"
        : "+f"(d.x), "+f"(d.y), "+f"(d.z), "+f"(d.w)
        : "r"(a.x), "r"(a.y), "r"(a.z), "r"(a.w), "r"(b0), "r"(b1));
}

// ---------------------------------------------------------------------------
__global__ void init_colmin_kernel() {
    int i = blockIdx.x * blockDim.x + threadIdx.x;
    if (i < MM) g_colmin[i] = 0x7f800000u;
}

// Pack e fragment-major (PTX m16n8k8.tf32 B layout): uint4 at
// ((j*16+kc)*128 + n)*4 + c = tf32{ e[.][16kc+c], [c+4], [c+8], [c+12] }
__global__ void prep_eB_kernel(const float* __restrict__ e) {
    int gid = blockIdx.x * blockDim.x + threadIdx.x;
    if (gid >= MM * DD / 4) return;
    int c  = gid & 3;
    int n  = (gid >> 2) & 127;
    int kc = (gid >> 9) & 15;
    int j  = gid >> 13;
    const float* row = e + (size_t)(j * 128 + n) * DD + kc * 16;
    float4 v;
    v.x = to_tf32(row[c]);
    v.y = to_tf32(row[c + 4]);
    v.z = to_tf32(row[c + 8]);
    v.w = to_tf32(row[c + 12]);
    ((float4*)g_eB)[gid] = v;
}

__global__ void esq_kernel(const float* __restrict__ e) {
    int warp = (blockIdx.x * blockDim.x + threadIdx.x) >> 5;
    int lane = threadIdx.x & 31;
    if (warp >= MM) return;
    const float* row = e + (size_t)warp * DD;
    float s = 0.f;
    #pragma unroll
    for (int i = 0; i < DD / 32; i++) { float v = row[lane + i * 32]; s += v * v; }
    #pragma unroll
    for (int o = 16; o > 0; o >>= 1) s += __shfl_down_sync(0xffffffffu, s, o);
    if (lane == 0) g_esq[warp] = s;
}

// ---------------------------------------------------------------------------
// Fused GEMM + distance + column-min. 256 CTAs x 288 threads (2 CTAs/SM).
// Warp 8 = cp.async producer; warps 0-7 = MMA consumers. mbarrier pipeline,
// zero block barriers in the mainloop.
__global__ void __launch_bounds__(288, 2)
gemm_dist_kernel(const float* __restrict__ z, float* __restrict__ out) {
    extern __shared__ char smem[];
    uint4* Ash   = (uint4*)(smem + SM_A);
    uint4* Bsh   = (uint4*)(smem + SM_B);
    float* zpart = (float*)(smem + SM_ZPART);
    float* zrow  = (float*)(smem + SM_ZROW);
    const uint32_t sbB = smem_u32(Bsh);
    const uint32_t mb_full  = smem_u32(smem + SM_MBAR);
    const uint32_t mb_empty = mb_full + 32;

    const int tid = threadIdx.x;
    const int wid = tid >> 5;
    const int lane = tid & 31;
    const int n0 = blockIdx.x << 6;  // 64-row tile
    const float* zbase = z + (size_t)(n0 >> 10) * (DD * 1024) + (n0 & 1023);

    if (tid == 0) {
        #pragma unroll
        for (int s = 0; s < 4; s++) {
            MBAR_INIT(mb_full + s * 8, 1);
            MBAR_INIT(mb_empty + s * 8, 8);
        }
    }

    // ---- prologue 1: z_sq partials (consumer threads) ----
    if (tid < 256) {
        float zacc = 0.f;
        const int an = tid & 63;
        const int dh = tid >> 6;
        #pragma unroll 8
        for (int it = 0; it < 64; it++) {
            float v = zbase[(size_t)(dh * 64 + it) * 1024 + an];
            zacc += v * v;
        }
        zpart[tid] = zacc;
    }
    __syncthreads();
    if (tid < 64)
        zrow[tid] = zpart[tid] + zpart[tid + 64] + zpart[tid + 128] + zpart[tid + 192];

    // ---- prologue 2: build A' fragment-major (PTX tf32 A layout) ----
    if (tid < 256) {
        #pragma unroll 4
        for (int it = 0; it < 16; it++) {
            int f = it * 256 + tid;
            int ln = f & 31, kstep = (f >> 5) & 31, rbg = f >> 10;
            int rr = rbg * 16 + (ln >> 2);
            int d0 = kstep * 8 + (ln & 3);
            uint4 a;
            a.x = __float_as_uint(to_tf32(__ldg(zbase + (size_t)d0 * 1024 + rr)));
            a.y = __float_as_uint(to_tf32(__ldg(zbase + (size_t)d0 * 1024 + rr + 8)));
            a.z = __float_as_uint(to_tf32(__ldg(zbase + (size_t)(d0 + 4) * 1024 + rr)));
            a.w = __float_as_uint(to_tf32(__ldg(zbase + (size_t)(d0 + 4) * 1024 + rr + 8)));
            Ash[(rbg * 32 + kstep) * 32 + ln] = a;
        }
    }
    __syncthreads();   // A', zrow, mbarriers ready — last block barrier

    if (wid == 8) {
        // ===================== PRODUCER =====================
        for (int u = 0; u < 256; u++) {
            const int buf = u & 3;
            MBAR_WAIT(mb_empty + buf * 8, ((u >> 2) & 1) ^ 1);
            const char* src = (const char*)g_eB + (size_t)u * 8192;
            const uint32_t dst = sbB + (uint32_t)buf * 8192;
            #pragma unroll
            for (int i = 0; i < 16; i++)
                CP_ASYNC16(dst + (uint32_t)(lane + i * 32) * 16,
                           src + (size_t)(lane + i * 32) * 16);
            CP_COMMIT();
            if (u >= 3) {
                CP_WAIT(3);
                if (elect_one_pred()) MBAR_ARRIVE(mb_full + ((u - 3) & 3) * 8);
            }
        }
        CP_WAIT(2); if (elect_one_pred()) MBAR_ARRIVE(mb_full + (253 & 3) * 8);
        CP_WAIT(1); if (elect_one_pred()) MBAR_ARRIVE(mb_full + (254 & 3) * 8);
        CP_WAIT(0); if (elect_one_pred()) MBAR_ARRIVE(mb_full + (255 & 3) * 8);
    } else {
        // ===================== CONSUMERS =====================
        const int wy = wid & 1;          // rows wy*32..+31
        const int wx = wid >> 1;         // cols wx*32..+31
        const int a_base = (wy * 2) * 1024 + lane;
        const int b_base = (wx * 32 + (lane >> 2)) * 4 + (lane & 3);
        const int r_lo = (lane >> 2);

        float4 acc[2][4];
        #pragma unroll
        for (int i = 0; i < 2; i++)
            #pragma unroll
            for (int nf = 0; nf < 4; nf++) acc[i][nf] = make_float4(0.f, 0.f, 0.f, 0.f);

        for (int u = 0; u < 256; u++) {
            const int kc = u & 15, buf = u & 3;
            MBAR_WAIT(mb_full + buf * 8, (u >> 2) & 1);

            uint4 bfr[4];
            #pragma unroll
            for (int nf = 0; nf < 4; nf++)
                bfr[nf] = Bsh[buf * 512 + b_base + nf * 32];
            uint4 af[2][2];
            #pragma unroll
            for (int i = 0; i < 2; i++)
                #pragma unroll
                for (int ks = 0; ks < 2; ks++)
                    af[i][ks] = Ash[a_base + i * 1024 + (kc * 2 + ks) * 32];

            #pragma unroll
            for (int i = 0; i < 2; i++)
                #pragma unroll
                for (int nf = 0; nf < 4; nf++) {
                    mma_tf32(acc[i][nf], af[i][0], bfr[nf].x, bfr[nf].y);
                    mma_tf32(acc[i][nf], af[i][1], bfr[nf].z, bfr[nf].w);
                }

            if (elect_one_pred()) MBAR_ARRIVE(mb_empty + buf * 8);

            if (kc == 15) {
                // ------- register-direct epilogue for m-chunk j -------
                const int j = u >> 4;
                float mn[4][2];
                #pragma unroll
                for (int i = 0; i < 2; i++) {
                    const float zr0 = zrow[wy * 32 + i * 16 + r_lo];
                    const float zr1 = zrow[wy * 32 + i * 16 + r_lo + 8];
                    float* orow0 = out + (size_t)(n0 + wy * 32 + i * 16 + r_lo) * MM + j * 128;
                    float* orow1 = orow0 + (size_t)8 * MM;
                    #pragma unroll
                    for (int nf = 0; nf < 4; nf++) {
                        const int col = wx * 32 + nf * 8 + (lane & 3) * 2;
                        float2 ev = *(const float2*)(g_esq + j * 128 + col);
                        float4 a = acc[i][nf];
                        float d00 = fmaxf(fmaf(-2.f, a.x, zr0 + ev.x), 0.f);
                        float d01 = fmaxf(fmaf(-2.f, a.y, zr0 + ev.y), 0.f);
                        float d10 = fmaxf(fmaf(-2.f, a.z, zr1 + ev.x), 0.f);
                        float d11 = fmaxf(fmaf(-2.f, a.w, zr1 + ev.y), 0.f);
                        *(float2*)(orow0 + col) = make_float2(d00, d01);
                        *(float2*)(orow1 + col) = make_float2(d10, d11);
                        float m0 = fminf(d00, d10), m1 = fminf(d01, d11);
                        if (i == 0) { mn[nf][0] = m0; mn[nf][1] = m1; }
                        else        { mn[nf][0] = fminf(mn[nf][0], m0);
                                      mn[nf][1] = fminf(mn[nf][1], m1); }
                        acc[i][nf] = make_float4(0.f, 0.f, 0.f, 0.f);
                    }
                }
                #pragma unroll
                for (int nf = 0; nf < 4; nf++) {
                    #pragma unroll
                    for (int h = 0; h < 2; h++) {
                        float m = mn[nf][h];
                        m = fminf(m, __shfl_xor_sync(0xffffffffu, m, 4));
                        m = fminf(m, __shfl_xor_sync(0xffffffffu, m, 8));
                        m = fminf(m, __shfl_xor_sync(0xffffffffu, m, 16));
                        mn[nf][h] = m;
                    }
                }
                if (r_lo == 0) {
                    #pragma unroll
                    for (int nf = 0; nf < 4; nf++) {
                        const int col = j * 128 + wx * 32 + nf * 8 + (lane & 3) * 2;
                        RED_MIN_U32(&g_colmin[col],     __float_as_uint(mn[nf][0]));
                        RED_MIN_U32(&g_colmin[col + 1], __float_as_uint(mn[nf][1]));
                    }
                }
            }
        }
    }
}

// ---------------------------------------------------------------------------
__global__ void loss_kernel(float* __restrict__ out_loss) {
    __shared__ float partial[256];
    int tid = threadIdx.x;
    float s = 0.f;
    for (int i = tid; i < MM; i += 256) s += __uint_as_float(g_colmin[i]);
    partial[tid] = s;
    __syncthreads();
    for (int o = 128; o > 0; o >>= 1) {
        if (tid < o) partial[tid] += partial[tid + o];
        __syncthreads();
    }
    if (tid == 0) out_loss[0] = partial[0] / (float)MM;
}

// ---------------------------------------------------------------------------
extern "C" void kernel_launch(void* const* d_in, const int* in_sizes, int n_in,
                              void* d_out, int out_size) {
    const float* z = (const float*)d_in[0];
    const float* e = (const float*)d_in[1];
    float* out = (float*)d_out;

    cudaFuncSetAttribute(gemm_dist_kernel,
                         cudaFuncAttributeMaxDynamicSharedMemorySize, SMEM_TOTAL);

    init_colmin_kernel<<<(MM + 255) / 256, 256>>>();
    prep_eB_kernel<<<(MM * DD / 4 + 255) / 256, 256>>>(e);
    esq_kernel<<<(MM * 32 + 255) / 256, 256>>>(e);

    gemm_dist_kernel<<<256, 288, SMEM_TOTAL>>>(z, out);

    loss_kernel<<<1, 256>>>(out + (size_t)NN * MM);
}

// round 13
// speedup vs baseline: 1.3895x; 1.3895x over previous
#include <cuda_runtime.h>
#include <cuda_bf16.h>
#include <cstdint>

#define NN 16384
#define MM 2048
#define DD 256

// 64-row n-tiles, 256 CTAs, 2 CTAs/SM, 256 threads.
// dynamic SMEM layout (bytes)
#define SM_A     0                 // A': 2048 uint4 (bf16) = 32768
#define SM_B     32768             // 8 stages x 256 uint4 (4KB) = 32768
#define SM_ZPART 65536             // 256 f32
#define SM_ZROW  66560             // 64 f32
#define SMEM_TOTAL 66816

__device__ __align__(16) uint2 g_eB[DD * MM / 4];  // fragment-packed bf16 B (1MB)
__device__ float    g_esq[MM];
__device__ unsigned g_colmin[MM];

// ---------------------------------------------------------------------------
__device__ __forceinline__ uint32_t bf2(float lo, float hi) {
    uint32_t r;
    asm("cvt.rn.bf16x2.f32 %0, %1, %2;" : "=r"(r) : "f"(hi), "f"(lo));
    return r;
}
__device__ __forceinline__ uint32_t smem_u32(const void* p) {
    uint32_t a;
    asm("{ .reg .u64 t; cvta.to.shared.u64 t, %1; cvt.u32.u64 %0, t; }" : "=r"(a) : "l"(p));
    return a;
}
#define CP_ASYNC16(dst, src) \
    asm volatile("cp.async.cg.shared.global [%0], [%1], 16;" :: "r"(dst), "l"(src))
#define CP_COMMIT() asm volatile("cp.async.commit_group;" ::: "memory")
#define CP_WAIT(n)  asm volatile("cp.async.wait_group %0;" :: "n"(n) : "memory")
#define RED_MIN_U32(ptr, val) \
    asm volatile("red.global.min.u32 [%0], %1;" :: "l"(ptr), "r"(val) : "memory")

__device__ __forceinline__ void mma_bf16(float4& d, const uint4& a, uint32_t b0, uint32_t b1) {
    asm volatile("mma.sync.aligned.m16n8k16.row.col.f32.bf16.bf16.f32 "
        "{%0,%1,%2,%3}, {%4,%5,%6,%7}, {%8,%9}, {%0,%1,%2,%3};"
        : "+f"(d.x), "+f"(d.y), "+f"(d.z), "+f"(d.w)
        : "r"(a.x), "r"(a.y), "r"(a.z), "r"(a.w), "r"(b0), "r"(b1));
}

// ---------------------------------------------------------------------------
__global__ void init_colmin_kernel() {
    int i = blockIdx.x * blockDim.x + threadIdx.x;
    if (i < MM) g_colmin[i] = 0x7f800000u;
}

// Pack e fragment-major for mma.m16n8k16.bf16 B operand:
// uint2 at ((j*16+kc)*128 + n)*4 + c = { bf16x2(e[.][16kc+2c], [+1]),
//                                        bf16x2(e[.][16kc+2c+8], [+9]) }
__global__ void prep_eB_kernel(const float* __restrict__ e) {
    int gid = blockIdx.x * blockDim.x + threadIdx.x;
    if (gid >= MM * DD / 4) return;
    int c  = gid & 3;
    int n  = (gid >> 2) & 127;
    int kc = (gid >> 9) & 15;
    int j  = gid >> 13;
    const float* row = e + (size_t)(j * 128 + n) * DD + kc * 16;
    uint2 v;
    v.x = bf2(row[2 * c],     row[2 * c + 1]);
    v.y = bf2(row[2 * c + 8], row[2 * c + 9]);
    g_eB[gid] = v;
}

__global__ void esq_kernel(const float* __restrict__ e) {
    int warp = (blockIdx.x * blockDim.x + threadIdx.x) >> 5;
    int lane = threadIdx.x & 31;
    if (warp >= MM) return;
    const float* row = e + (size_t)warp * DD;
    float s = 0.f;
    #pragma unroll
    for (int i = 0; i < DD / 32; i++) { float v = row[lane + i * 32]; s += v * v; }
    #pragma unroll
    for (int o = 16; o > 0; o >>= 1) s += __shfl_down_sync(0xffffffffu, s, o);
    if (lane == 0) g_esq[warp] = s;
}

// ---------------------------------------------------------------------------
// Fused GEMM + distance + column-min. 256 CTAs x 256 threads (2 CTAs/SM).
__global__ void __launch_bounds__(256, 2)
gemm_dist_kernel(const float* __restrict__ z, float* __restrict__ out) {
    extern __shared__ char smem[];
    uint4* Ash   = (uint4*)(smem + SM_A);
    uint2* Bsh   = (uint2*)(smem + SM_B);
    float* zpart = (float*)(smem + SM_ZPART);
    float* zrow  = (float*)(smem + SM_ZROW);
    const uint32_t sbB = smem_u32(Bsh);

    const int tid = threadIdx.x;
    const int wid = tid >> 5;
    const int lane = tid & 31;
    const int wy = wid & 1;          // rows wy*32..+31
    const int wx = wid >> 1;         // cols wx*32..+31
    const int n0 = blockIdx.x << 6;  // 64-row tile
    const float* zbase = z + (size_t)(n0 >> 10) * (DD * 1024) + (n0 & 1023);

    // ---- B chunk loader: k16 bf16 chunks (4KB = 256 uint4), 1 per thread ----
    auto issueB = [&](int u) {
        int buf = u & 7;
        CP_ASYNC16(sbB + (uint32_t)(buf * 256 + tid) * 16,
                   (const char*)g_eB + (size_t)u * 4096 + (size_t)tid * 16);
        CP_COMMIT();
    };
    #pragma unroll
    for (int p = 0; p < 7; p++) issueB(p);

    // ---- prologue 1: z_sq partials ----
    {
        float zacc = 0.f;
        const int an = tid & 63;
        const int dh = tid >> 6;
        #pragma unroll 8
        for (int it = 0; it < 64; it++) {
            float v = zbase[(size_t)(dh * 64 + it) * 1024 + an];
            zacc += v * v;
        }
        zpart[tid] = zacc;
    }
    __syncthreads();
    if (tid < 64)
        zrow[tid] = zpart[tid] + zpart[tid + 64] + zpart[tid + 128] + zpart[tid + 192];

    // ---- prologue 2: build A' fragment-major (m16n8k16 bf16 A layout) ----
    // fragment f = (rbg*16 + kstep)*32 + ln ; rbg 0..3 (16 rows), kstep 0..15 (k16)
    #pragma unroll 4
    for (int it = 0; it < 8; it++) {
        int f = it * 256 + tid;
        int ln = f & 31, kstep = (f >> 5) & 15, rbg = f >> 9;
        int rr = rbg * 16 + (ln >> 2);
        int d0 = kstep * 16 + (ln & 3) * 2;
        float z00 = __ldg(zbase + (size_t)d0 * 1024 + rr);
        float z01 = __ldg(zbase + (size_t)(d0 + 1) * 1024 + rr);
        float z10 = __ldg(zbase + (size_t)d0 * 1024 + rr + 8);
        float z11 = __ldg(zbase + (size_t)(d0 + 1) * 1024 + rr + 8);
        float z02 = __ldg(zbase + (size_t)(d0 + 8) * 1024 + rr);
        float z03 = __ldg(zbase + (size_t)(d0 + 9) * 1024 + rr);
        float z12 = __ldg(zbase + (size_t)(d0 + 8) * 1024 + rr + 8);
        float z13 = __ldg(zbase + (size_t)(d0 + 9) * 1024 + rr + 8);
        uint4 a;
        a.x = bf2(z00, z01);   // (rr,   k d0,d0+1)
        a.y = bf2(z10, z11);   // (rr+8, k d0,d0+1)
        a.z = bf2(z02, z03);   // (rr,   k d0+8,d0+9)
        a.w = bf2(z12, z13);   // (rr+8, k d0+8,d0+9)
        Ash[(rbg * 16 + kstep) * 32 + ln] = a;
    }

    // ---- accumulators: warp tile 32 x 32 ----
    float4 acc[2][4];
    #pragma unroll
    for (int i = 0; i < 2; i++)
        #pragma unroll
        for (int nf = 0; nf < 4; nf++) acc[i][nf] = make_float4(0.f, 0.f, 0.f, 0.f);

    const int a_base = (wy * 2) * 512 + lane;          // rbg = wy*2 + i, i stride 512
    const int b_base = (wx * 32 + (lane >> 2)) * 4 + (lane & 3);
    const int r_lo = (lane >> 2);

    #pragma unroll 2
    for (int u = 0; u < 256; u++) {
        const int kc = u & 15, buf = u & 7;
        CP_WAIT(6);                        // chunk u complete (issued 7 iters ago)
        __syncthreads();
        if (u + 7 < 256) issueB(u + 7);

        uint2 bfr[4];
        #pragma unroll
        for (int nf = 0; nf < 4; nf++)
            bfr[nf] = Bsh[buf * 512 + b_base + nf * 32];
        uint4 af[2];
        #pragma unroll
        for (int i = 0; i < 2; i++)
            af[i] = Ash[a_base + i * 512 + kc * 32];

        #pragma unroll
        for (int i = 0; i < 2; i++)
            #pragma unroll
            for (int nf = 0; nf < 4; nf++)
                mma_bf16(acc[i][nf], af[i], bfr[nf].x, bfr[nf].y);

        if (kc == 15) {
            // ------- register-direct epilogue for m-chunk j (no barriers) -------
            const int j = u >> 4;
            float mn[4][2];
            #pragma unroll
            for (int i = 0; i < 2; i++) {
                const float zr0 = zrow[wy * 32 + i * 16 + r_lo];
                const float zr1 = zrow[wy * 32 + i * 16 + r_lo + 8];
                float* orow0 = out + (size_t)(n0 + wy * 32 + i * 16 + r_lo) * MM + j * 128;
                float* orow1 = orow0 + (size_t)8 * MM;
                #pragma unroll
                for (int nf = 0; nf < 4; nf++) {
                    const int col = wx * 32 + nf * 8 + (lane & 3) * 2;
                    float2 ev = *(const float2*)(g_esq + j * 128 + col);
                    float4 a = acc[i][nf];
                    float d00 = fmaxf(fmaf(-2.f, a.x, zr0 + ev.x), 0.f);
                    float d01 = fmaxf(fmaf(-2.f, a.y, zr0 + ev.y), 0.f);
                    float d10 = fmaxf(fmaf(-2.f, a.z, zr1 + ev.x), 0.f);
                    float d11 = fmaxf(fmaf(-2.f, a.w, zr1 + ev.y), 0.f);
                    *(float2*)(orow0 + col) = make_float2(d00, d01);
                    *(float2*)(orow1 + col) = make_float2(d10, d11);
                    float m0 = fminf(d00, d10), m1 = fminf(d01, d11);
                    if (i == 0) { mn[nf][0] = m0; mn[nf][1] = m1; }
                    else        { mn[nf][0] = fminf(mn[nf][0], m0);
                                  mn[nf][1] = fminf(mn[nf][1], m1); }
                    acc[i][nf] = make_float4(0.f, 0.f, 0.f, 0.f);
                }
            }
            #pragma unroll
            for (int nf = 0; nf < 4; nf++) {
                #pragma unroll
                for (int h = 0; h < 2; h++) {
                    float m = mn[nf][h];
                    m = fminf(m, __shfl_xor_sync(0xffffffffu, m, 4));
                    m = fminf(m, __shfl_xor_sync(0xffffffffu, m, 8));
                    m = fminf(m, __shfl_xor_sync(0xffffffffu, m, 16));
                    mn[nf][h] = m;
                }
            }
            if (r_lo == 0) {
                #pragma unroll
                for (int nf = 0; nf < 4; nf++) {
                    const int col = j * 128 + wx * 32 + nf * 8 + (lane & 3) * 2;
                    RED_MIN_U32(&g_colmin[col],     __float_as_uint(mn[nf][0]));
                    RED_MIN_U32(&g_colmin[col + 1], __float_as_uint(mn[nf][1]));
                }
            }
        }
    }
}

// ---------------------------------------------------------------------------
__global__ void loss_kernel(float* __restrict__ out_loss) {
    __shared__ float partial[256];
    int tid = threadIdx.x;
    float s = 0.f;
    for (int i = tid; i < MM; i += 256) s += __uint_as_float(g_colmin[i]);
    partial[tid] = s;
    __syncthreads();
    for (int o = 128; o > 0; o >>= 1) {
        if (tid < o) partial[tid] += partial[tid + o];
        __syncthreads();
    }
    if (tid == 0) out_loss[0] = partial[0] / (float)MM;
}

// ---------------------------------------------------------------------------
extern "C" void kernel_launch(void* const* d_in, const int* in_sizes, int n_in,
                              void* d_out, int out_size) {
    const float* z = (const float*)d_in[0];
    const float* e = (const float*)d_in[1];
    float* out = (float*)d_out;

    cudaFuncSetAttribute(gemm_dist_kernel,
                         cudaFuncAttributeMaxDynamicSharedMemorySize, SMEM_TOTAL);

    init_colmin_kernel<<<(MM + 255) / 256, 256>>>();
    prep_eB_kernel<<<(MM * DD / 4 + 255) / 256, 256>>>(e);
    esq_kernel<<<(MM * 32 + 255) / 256, 256>>>(e);

    gemm_dist_kernel<<<256, 256, SMEM_TOTAL>>>(z, out);

    loss_kernel<<<1, 256>>>(out + (size_t)NN * MM);
}

// round 14
// speedup vs baseline: 1.4767x; 1.0628x over previous
#include <cuda_runtime.h>
#include <cuda_bf16.h>
#include <cstdint>

#define NN 16384
#define MM 2048
#define DD 256

// 64-row n-tiles, 256 CTAs, 2 CTAs/SM, 256 threads. CTA tile 64x256 per m-chunk.
// dynamic SMEM layout (bytes)
#define SM_A     0                 // A': 2048 uint4 (bf16) = 32768
#define SM_B     32768             // 8 stages x 512 uint4 (8KB) = 65536
#define SM_ZPART 98304             // 256 f32
#define SM_ZROW  99328             // 64 f32
#define SMEM_TOTAL 99584

__device__ __align__(16) uint2 g_eB[DD * MM / 4];  // fragment-packed bf16 B (1MB)
__device__ float    g_esq[MM];
__device__ unsigned g_colmin[MM];

// ---------------------------------------------------------------------------
__device__ __forceinline__ uint32_t bf2(float lo, float hi) {
    uint32_t r;
    asm("cvt.rn.bf16x2.f32 %0, %1, %2;" : "=r"(r) : "f"(hi), "f"(lo));
    return r;
}
__device__ __forceinline__ uint32_t smem_u32(const void* p) {
    uint32_t a;
    asm("{ .reg .u64 t; cvta.to.shared.u64 t, %1; cvt.u32.u64 %0, t; }" : "=r"(a) : "l"(p));
    return a;
}
#define CP_ASYNC16(dst, src) \
    asm volatile("cp.async.cg.shared.global [%0], [%1], 16;" :: "r"(dst), "l"(src))
#define CP_COMMIT() asm volatile("cp.async.commit_group;" ::: "memory")
#define CP_WAIT(n)  asm volatile("cp.async.wait_group %0;" :: "n"(n) : "memory")
#define RED_MIN_U32(ptr, val) \
    asm volatile("red.global.min.u32 [%0], %1;" :: "l"(ptr), "r"(val) : "memory")

__device__ __forceinline__ void mma_bf16(float4& d, const uint4& a, uint32_t b0, uint32_t b1) {
    asm volatile("mma.sync.aligned.m16n8k16.row.col.f32.bf16.bf16.f32 "
        "{%0,%1,%2,%3}, {%4,%5,%6,%7}, {%8,%9}, {%0,%1,%2,%3};"
        : "+f"(d.x), "+f"(d.y), "+f"(d.z), "+f"(d.w)
        : "r"(a.x), "r"(a.y), "r"(a.z), "r"(a.w), "r"(b0), "r"(b1));
}

// ---------------------------------------------------------------------------
__global__ void init_colmin_kernel() {
    int i = blockIdx.x * blockDim.x + threadIdx.x;
    if (i < MM) g_colmin[i] = 0x7f800000u;
}

// Pack e fragment-major for mma.m16n8k16.bf16 B operand, m-chunks of 256:
// uint2 at ((j*16+kc)*256 + n)*4 + c = { bf16x2(e[j*256+n][16kc+2c], [+1]),
//                                        bf16x2(e[j*256+n][16kc+2c+8], [+9]) }
__global__ void prep_eB_kernel(const float* __restrict__ e) {
    int gid = blockIdx.x * blockDim.x + threadIdx.x;
    if (gid >= MM * DD / 4) return;
    int c  = gid & 3;
    int n  = (gid >> 2) & 255;
    int kc = (gid >> 10) & 15;
    int j  = gid >> 14;
    const float* row = e + (size_t)(j * 256 + n) * DD + kc * 16;
    uint2 v;
    v.x = bf2(row[2 * c],     row[2 * c + 1]);
    v.y = bf2(row[2 * c + 8], row[2 * c + 9]);
    g_eB[gid] = v;
}

__global__ void esq_kernel(const float* __restrict__ e) {
    int warp = (blockIdx.x * blockDim.x + threadIdx.x) >> 5;
    int lane = threadIdx.x & 31;
    if (warp >= MM) return;
    const float* row = e + (size_t)warp * DD;
    float s = 0.f;
    #pragma unroll
    for (int i = 0; i < DD / 32; i++) { float v = row[lane + i * 32]; s += v * v; }
    #pragma unroll
    for (int o = 16; o > 0; o >>= 1) s += __shfl_down_sync(0xffffffffu, s, o);
    if (lane == 0) g_esq[warp] = s;
}

// ---------------------------------------------------------------------------
// Fused GEMM + distance + column-min. 256 CTAs x 256 threads (2 CTAs/SM).
// Warp tile 32x64; k32 per rendezvous (2 chunks).
__global__ void __launch_bounds__(256, 2)
gemm_dist_kernel(const float* __restrict__ z, float* __restrict__ out) {
    extern __shared__ char smem[];
    uint4* Ash   = (uint4*)(smem + SM_A);
    uint2* Bsh   = (uint2*)(smem + SM_B);
    float* zpart = (float*)(smem + SM_ZPART);
    float* zrow  = (float*)(smem + SM_ZROW);
    const uint32_t sbB = smem_u32(Bsh);

    const int tid = threadIdx.x;
    const int wid = tid >> 5;
    const int lane = tid & 31;
    const int wy = wid & 1;          // rows wy*32..+31
    const int wx = wid >> 1;         // cols wx*64..+63 (within 256-wide chunk)
    const int n0 = blockIdx.x << 6;  // 64-row tile
    const float* zbase = z + (size_t)(n0 >> 10) * (DD * 1024) + (n0 & 1023);

    // ---- B loader: one k16 chunk = 8KB = 512 uint4 (2 per thread);
    //      pairs of chunks share one commit group ----
    auto issuePair = [&](int v) {          // v = k32 pair index, chunks 2v, 2v+1
        #pragma unroll
        for (int h = 0; h < 2; h++) {
            int g = 2 * v + h;
            int st = g & 7;
            const char* src = (const char*)g_eB + (size_t)g * 8192;
            uint32_t dst = sbB + (uint32_t)st * 8192;
            CP_ASYNC16(dst + (uint32_t)tid * 16,         src + (size_t)tid * 16);
            CP_ASYNC16(dst + (uint32_t)(tid + 256) * 16, src + (size_t)(tid + 256) * 16);
        }
        CP_COMMIT();
    };
    issuePair(0); issuePair(1); issuePair(2);

    // ---- prologue 1: z_sq partials ----
    {
        float zacc = 0.f;
        const int an = tid & 63;
        const int dh = tid >> 6;
        #pragma unroll 8
        for (int it = 0; it < 64; it++) {
            float v = zbase[(size_t)(dh * 64 + it) * 1024 + an];
            zacc += v * v;
        }
        zpart[tid] = zacc;
    }
    __syncthreads();
    if (tid < 64)
        zrow[tid] = zpart[tid] + zpart[tid + 64] + zpart[tid + 128] + zpart[tid + 192];

    // ---- prologue 2: build A' fragment-major (m16n8k16 bf16 A layout) ----
    #pragma unroll 4
    for (int it = 0; it < 8; it++) {
        int f = it * 256 + tid;
        int ln = f & 31, kstep = (f >> 5) & 15, rbg = f >> 9;
        int rr = rbg * 16 + (ln >> 2);
        int d0 = kstep * 16 + (ln & 3) * 2;
        float z00 = __ldg(zbase + (size_t)d0 * 1024 + rr);
        float z01 = __ldg(zbase + (size_t)(d0 + 1) * 1024 + rr);
        float z10 = __ldg(zbase + (size_t)d0 * 1024 + rr + 8);
        float z11 = __ldg(zbase + (size_t)(d0 + 1) * 1024 + rr + 8);
        float z02 = __ldg(zbase + (size_t)(d0 + 8) * 1024 + rr);
        float z03 = __ldg(zbase + (size_t)(d0 + 9) * 1024 + rr);
        float z12 = __ldg(zbase + (size_t)(d0 + 8) * 1024 + rr + 8);
        float z13 = __ldg(zbase + (size_t)(d0 + 9) * 1024 + rr + 8);
        uint4 a;
        a.x = bf2(z00, z01);
        a.y = bf2(z10, z11);
        a.z = bf2(z02, z03);
        a.w = bf2(z12, z13);
        Ash[(rbg * 16 + kstep) * 32 + ln] = a;
    }

    // ---- accumulators: warp tile 32 x 64 (2 rowblocks x 8 n-frags) ----
    float4 acc[2][8];
    #pragma unroll
    for (int i = 0; i < 2; i++)
        #pragma unroll
        for (int nf = 0; nf < 8; nf++) acc[i][nf] = make_float4(0.f, 0.f, 0.f, 0.f);

    const int a_base = (wy * 2) * 512 + lane;          // rbg = wy*2 + i, stride 512
    const int b_base = (wx * 64 + (lane >> 2)) * 4 + (lane & 3);
    const int r_lo = (lane >> 2);

    for (int v = 0; v < 64; v++) {
        if (v < 62)      { CP_WAIT(2); }
        else if (v == 62){ CP_WAIT(1); }
        else             { CP_WAIT(0); }
        __syncthreads();
        if (v + 3 < 64) issuePair(v + 3);

        #pragma unroll
        for (int h = 0; h < 2; h++) {
            const int g = 2 * v + h;
            const int kc = g & 15, st = g & 7;
            uint2 bfr[8];
            #pragma unroll
            for (int nf = 0; nf < 8; nf++)
                bfr[nf] = Bsh[st * 1024 + b_base + nf * 32];
            uint4 af[2];
            #pragma unroll
            for (int i = 0; i < 2; i++)
                af[i] = Ash[a_base + i * 512 + kc * 32];
            #pragma unroll
            for (int i = 0; i < 2; i++)
                #pragma unroll
                for (int nf = 0; nf < 8; nf++)
                    mma_bf16(acc[i][nf], af[i], bfr[nf].x, bfr[nf].y);
        }

        if ((v & 7) == 7) {
            // ------- register-direct epilogue for m-chunk j (256 wide) -------
            const int j = v >> 3;
            float mn[8][2];
            #pragma unroll
            for (int i = 0; i < 2; i++) {
                const float zr0 = zrow[wy * 32 + i * 16 + r_lo];
                const float zr1 = zrow[wy * 32 + i * 16 + r_lo + 8];
                float* orow0 = out + (size_t)(n0 + wy * 32 + i * 16 + r_lo) * MM + j * 256;
                float* orow1 = orow0 + (size_t)8 * MM;
                #pragma unroll
                for (int nf = 0; nf < 8; nf++) {
                    const int col = wx * 64 + nf * 8 + (lane & 3) * 2;
                    float2 ev = *(const float2*)(g_esq + j * 256 + col);
                    float4 a = acc[i][nf];
                    float d00 = fmaxf(fmaf(-2.f, a.x, zr0 + ev.x), 0.f);
                    float d01 = fmaxf(fmaf(-2.f, a.y, zr0 + ev.y), 0.f);
                    float d10 = fmaxf(fmaf(-2.f, a.z, zr1 + ev.x), 0.f);
                    float d11 = fmaxf(fmaf(-2.f, a.w, zr1 + ev.y), 0.f);
                    *(float2*)(orow0 + col) = make_float2(d00, d01);
                    *(float2*)(orow1 + col) = make_float2(d10, d11);
                    float m0 = fminf(d00, d10), m1 = fminf(d01, d11);
                    if (i == 0) { mn[nf][0] = m0; mn[nf][1] = m1; }
                    else        { mn[nf][0] = fminf(mn[nf][0], m0);
                                  mn[nf][1] = fminf(mn[nf][1], m1); }
                    acc[i][nf] = make_float4(0.f, 0.f, 0.f, 0.f);
                }
            }
            #pragma unroll
            for (int nf = 0; nf < 8; nf++) {
                #pragma unroll
                for (int h = 0; h < 2; h++) {
                    float m = mn[nf][h];
                    m = fminf(m, __shfl_xor_sync(0xffffffffu, m, 4));
                    m = fminf(m, __shfl_xor_sync(0xffffffffu, m, 8));
                    m = fminf(m, __shfl_xor_sync(0xffffffffu, m, 16));
                    mn[nf][h] = m;
                }
            }
            if (r_lo == 0) {
                #pragma unroll
                for (int nf = 0; nf < 8; nf++) {
                    const int col = j * 256 + wx * 64 + nf * 8 + (lane & 3) * 2;
                    RED_MIN_U32(&g_colmin[col],     __float_as_uint(mn[nf][0]));
                    RED_MIN_U32(&g_colmin[col + 1], __float_as_uint(mn[nf][1]));
                }
            }
        }
    }
}

// ---------------------------------------------------------------------------
__global__ void loss_kernel(float* __restrict__ out_loss) {
    __shared__ float partial[256];
    int tid = threadIdx.x;
    float s = 0.f;
    for (int i = tid; i < MM; i += 256) s += __uint_as_float(g_colmin[i]);
    partial[tid] = s;
    __syncthreads();
    for (int o = 128; o > 0; o >>= 1) {
        if (tid < o) partial[tid] += partial[tid + o];
        __syncthreads();
    }
    if (tid == 0) out_loss[0] = partial[0] / (float)MM;
}

// ---------------------------------------------------------------------------
extern "C" void kernel_launch(void* const* d_in, const int* in_sizes, int n_in,
                              void* d_out, int out_size) {
    const float* z = (const float*)d_in[0];
    const float* e = (const float*)d_in[1];
    float* out = (float*)d_out;

    cudaFuncSetAttribute(gemm_dist_kernel,
                         cudaFuncAttributeMaxDynamicSharedMemorySize, SMEM_TOTAL);

    init_colmin_kernel<<<(MM + 255) / 256, 256>>>();
    prep_eB_kernel<<<(MM * DD / 4 + 255) / 256, 256>>>(e);
    esq_kernel<<<(MM * 32 + 255) / 256, 256>>>(e);

    gemm_dist_kernel<<<256, 256, SMEM_TOTAL>>>(z, out);

    loss_kernel<<<1, 256>>>(out + (size_t)NN * MM);
}

// round 15
// speedup vs baseline: 1.5907x; 1.0772x over previous
#include <cuda_runtime.h>
#include <cuda_bf16.h>
#include <cstdint>

#define NN 16384
#define MM 2048
#define DD 256

// 64-row n-tiles, 256 CTAs, 2 CTAs/SM, 256 threads. CTA m-chunk tile 64x256.
// B never touches SMEM: fragment LDGs from L2-resident g_eB, reg double-buffer.
// dynamic SMEM layout (bytes)
#define SM_A     0                 // A': 2048 uint4 (bf16) = 32768
#define SM_ZPART 32768             // 256 f32
#define SM_ZROW  33792             // 64 f32
#define SMEM_TOTAL 34048

__device__ __align__(16) uint2 g_eB[DD * MM / 4];  // fragment-packed bf16 B (1MB)
__device__ float    g_esq[MM];
__device__ unsigned g_colmin[MM];

// ---------------------------------------------------------------------------
__device__ __forceinline__ uint32_t bf2(float lo, float hi) {
    uint32_t r;
    asm("cvt.rn.bf16x2.f32 %0, %1, %2;" : "=r"(r) : "f"(hi), "f"(lo));
    return r;
}
#define RED_MIN_U32(ptr, val) \
    asm volatile("red.global.min.u32 [%0], %1;" :: "l"(ptr), "r"(val) : "memory")

__device__ __forceinline__ void mma_bf16(float4& d, const uint4& a, uint32_t b0, uint32_t b1) {
    asm volatile("mma.sync.aligned.m16n8k16.row.col.f32.bf16.bf16.f32 "
        "{%0,%1,%2,%3}, {%4,%5,%6,%7}, {%8,%9}, {%0,%1,%2,%3};"
        : "+f"(d.x), "+f"(d.y), "+f"(d.z), "+f"(d.w)
        : "r"(a.x), "r"(a.y), "r"(a.z), "r"(a.w), "r"(b0), "r"(b1));
}

// ---------------------------------------------------------------------------
__global__ void init_colmin_kernel() {
    int i = blockIdx.x * blockDim.x + threadIdx.x;
    if (i < MM) g_colmin[i] = 0x7f800000u;
}

// Pack e fragment-major for mma.m16n8k16.bf16 B operand, m-chunks of 256:
// uint2 at ((j*16+kc)*256 + n)*4 + c = { bf16x2(e[j*256+n][16kc+2c], [+1]),
//                                        bf16x2(e[j*256+n][16kc+2c+8], [+9]) }
__global__ void prep_eB_kernel(const float* __restrict__ e) {
    int gid = blockIdx.x * blockDim.x + threadIdx.x;
    if (gid >= MM * DD / 4) return;
    int c  = gid & 3;
    int n  = (gid >> 2) & 255;
    int kc = (gid >> 10) & 15;
    int j  = gid >> 14;
    const float* row = e + (size_t)(j * 256 + n) * DD + kc * 16;
    uint2 v;
    v.x = bf2(row[2 * c],     row[2 * c + 1]);
    v.y = bf2(row[2 * c + 8], row[2 * c + 9]);
    g_eB[gid] = v;
}

__global__ void esq_kernel(const float* __restrict__ e) {
    int warp = (blockIdx.x * blockDim.x + threadIdx.x) >> 5;
    int lane = threadIdx.x & 31;
    if (warp >= MM) return;
    const float* row = e + (size_t)warp * DD;
    float s = 0.f;
    #pragma unroll
    for (int i = 0; i < DD / 32; i++) { float v = row[lane + i * 32]; s += v * v; }
    #pragma unroll
    for (int o = 16; o > 0; o >>= 1) s += __shfl_down_sync(0xffffffffu, s, o);
    if (lane == 0) g_esq[warp] = s;
}

// ---------------------------------------------------------------------------
// Fused GEMM + distance + column-min. 256 CTAs x 256 threads (2 CTAs/SM).
// Warp tile 32x64. No cp.async, no mainloop barriers: B fragments stream
// straight from L2 via coalesced LDG.64 with register double-buffering.
__global__ void __launch_bounds__(256, 2)
gemm_dist_kernel(const float* __restrict__ z, float* __restrict__ out) {
    extern __shared__ char smem[];
    uint4* Ash   = (uint4*)(smem + SM_A);
    float* zpart = (float*)(smem + SM_ZPART);
    float* zrow  = (float*)(smem + SM_ZROW);

    const int tid = threadIdx.x;
    const int wid = tid >> 5;
    const int lane = tid & 31;
    const int wy = wid & 1;          // rows wy*32..+31
    const int wx = wid >> 1;         // cols wx*64..+63 (within 256-wide chunk)
    const int n0 = blockIdx.x << 6;  // 64-row tile
    const float* zbase = z + (size_t)(n0 >> 10) * (DD * 1024) + (n0 & 1023);

    // ---- prologue 1: z_sq partials ----
    {
        float zacc = 0.f;
        const int an = tid & 63;
        const int dh = tid >> 6;
        #pragma unroll 8
        for (int it = 0; it < 64; it++) {
            float v = zbase[(size_t)(dh * 64 + it) * 1024 + an];
            zacc += v * v;
        }
        zpart[tid] = zacc;
    }
    __syncthreads();
    if (tid < 64)
        zrow[tid] = zpart[tid] + zpart[tid + 64] + zpart[tid + 128] + zpart[tid + 192];

    // ---- prologue 2: build A' fragment-major (m16n8k16 bf16 A layout) ----
    #pragma unroll 4
    for (int it = 0; it < 8; it++) {
        int f = it * 256 + tid;
        int ln = f & 31, kstep = (f >> 5) & 15, rbg = f >> 9;
        int rr = rbg * 16 + (ln >> 2);
        int d0 = kstep * 16 + (ln & 3) * 2;
        float z00 = __ldg(zbase + (size_t)d0 * 1024 + rr);
        float z01 = __ldg(zbase + (size_t)(d0 + 1) * 1024 + rr);
        float z10 = __ldg(zbase + (size_t)d0 * 1024 + rr + 8);
        float z11 = __ldg(zbase + (size_t)(d0 + 1) * 1024 + rr + 8);
        float z02 = __ldg(zbase + (size_t)(d0 + 8) * 1024 + rr);
        float z03 = __ldg(zbase + (size_t)(d0 + 9) * 1024 + rr);
        float z12 = __ldg(zbase + (size_t)(d0 + 8) * 1024 + rr + 8);
        float z13 = __ldg(zbase + (size_t)(d0 + 9) * 1024 + rr + 8);
        uint4 a;
        a.x = bf2(z00, z01);
        a.y = bf2(z10, z11);
        a.z = bf2(z02, z03);
        a.w = bf2(z12, z13);
        Ash[(rbg * 16 + kstep) * 32 + ln] = a;
    }
    __syncthreads();   // A', zrow ready — LAST block barrier

    // ---- accumulators: warp tile 32 x 64 (2 rowblocks x 8 n-frags) ----
    float4 acc[2][8];
    #pragma unroll
    for (int i = 0; i < 2; i++)
        #pragma unroll
        for (int nf = 0; nf < 8; nf++) acc[i][nf] = make_float4(0.f, 0.f, 0.f, 0.f);

    const int a_base = (wy * 2) * 512 + lane;          // rbg = wy*2 + i, stride 512
    const int b_base = (wx * 64 + (lane >> 2)) * 4 + (lane & 3);
    const int r_lo = (lane >> 2);
    const uint2* gB = g_eB + b_base;

    // B register double buffer (chunk granularity: k16, 8 frags)
    uint2 bufA[8], bufB[8];
    #pragma unroll
    for (int nf = 0; nf < 8; nf++) bufA[nf] = __ldg(gB + nf * 32);

    // 128 k16-chunks total (8 m-chunks x 16 k-chunks); unroll by 2 for static bufs
    for (int v = 0; v < 64; v++) {
        const int g0 = 2 * v;
        // prefetch g0+1 into bufB
        {
            const uint2* p = gB + (size_t)(g0 + 1) * 1024;
            #pragma unroll
            for (int nf = 0; nf < 8; nf++) bufB[nf] = __ldg(p + nf * 32);
        }
        // compute chunk g0 from bufA
        {
            const int kc = g0 & 15;
            uint4 af[2];
            #pragma unroll
            for (int i = 0; i < 2; i++) af[i] = Ash[a_base + i * 512 + kc * 32];
            #pragma unroll
            for (int i = 0; i < 2; i++)
                #pragma unroll
                for (int nf = 0; nf < 8; nf++)
                    mma_bf16(acc[i][nf], af[i], bufA[nf].x, bufA[nf].y);
        }
        // prefetch g0+2 into bufA
        if (v < 63) {
            const uint2* p = gB + (size_t)(g0 + 2) * 1024;
            #pragma unroll
            for (int nf = 0; nf < 8; nf++) bufA[nf] = __ldg(p + nf * 32);
        }
        // compute chunk g0+1 from bufB
        {
            const int kc = (g0 + 1) & 15;
            uint4 af[2];
            #pragma unroll
            for (int i = 0; i < 2; i++) af[i] = Ash[a_base + i * 512 + kc * 32];
            #pragma unroll
            for (int i = 0; i < 2; i++)
                #pragma unroll
                for (int nf = 0; nf < 8; nf++)
                    mma_bf16(acc[i][nf], af[i], bufB[nf].x, bufB[nf].y);
        }

        if ((v & 7) == 7) {
            // ------- register-direct epilogue for m-chunk j (256 wide) -------
            const int j = v >> 3;
            float mn[8][2];
            #pragma unroll
            for (int i = 0; i < 2; i++) {
                const float zr0 = zrow[wy * 32 + i * 16 + r_lo];
                const float zr1 = zrow[wy * 32 + i * 16 + r_lo + 8];
                float* orow0 = out + (size_t)(n0 + wy * 32 + i * 16 + r_lo) * MM + j * 256;
                float* orow1 = orow0 + (size_t)8 * MM;
                #pragma unroll
                for (int nf = 0; nf < 8; nf++) {
                    const int col = wx * 64 + nf * 8 + (lane & 3) * 2;
                    float2 ev = *(const float2*)(g_esq + j * 256 + col);
                    float4 a = acc[i][nf];
                    float d00 = fmaxf(fmaf(-2.f, a.x, zr0 + ev.x), 0.f);
                    float d01 = fmaxf(fmaf(-2.f, a.y, zr0 + ev.y), 0.f);
                    float d10 = fmaxf(fmaf(-2.f, a.z, zr1 + ev.x), 0.f);
                    float d11 = fmaxf(fmaf(-2.f, a.w, zr1 + ev.y), 0.f);
                    *(float2*)(orow0 + col) = make_float2(d00, d01);
                    *(float2*)(orow1 + col) = make_float2(d10, d11);
                    float m0 = fminf(d00, d10), m1 = fminf(d01, d11);
                    if (i == 0) { mn[nf][0] = m0; mn[nf][1] = m1; }
                    else        { mn[nf][0] = fminf(mn[nf][0], m0);
                                  mn[nf][1] = fminf(mn[nf][1], m1); }
                    acc[i][nf] = make_float4(0.f, 0.f, 0.f, 0.f);
                }
            }
            #pragma unroll
            for (int nf = 0; nf < 8; nf++) {
                #pragma unroll
                for (int h = 0; h < 2; h++) {
                    float m = mn[nf][h];
                    m = fminf(m, __shfl_xor_sync(0xffffffffu, m, 4));
                    m = fminf(m, __shfl_xor_sync(0xffffffffu, m, 8));
                    m = fminf(m, __shfl_xor_sync(0xffffffffu, m, 16));
                    mn[nf][h] = m;
                }
            }
            if (r_lo == 0) {
                #pragma unroll
                for (int nf = 0; nf < 8; nf++) {
                    const int col = j * 256 + wx * 64 + nf * 8 + (lane & 3) * 2;
                    RED_MIN_U32(&g_colmin[col],     __float_as_uint(mn[nf][0]));
                    RED_MIN_U32(&g_colmin[col + 1], __float_as_uint(mn[nf][1]));
                }
            }
        }
    }
}

// ---------------------------------------------------------------------------
__global__ void loss_kernel(float* __restrict__ out_loss) {
    __shared__ float partial[256];
    int tid = threadIdx.x;
    float s = 0.f;
    for (int i = tid; i < MM; i += 256) s += __uint_as_float(g_colmin[i]);
    partial[tid] = s;
    __syncthreads();
    for (int o = 128; o > 0; o >>= 1) {
        if (tid < o) partial[tid] += partial[tid + o];
        __syncthreads();
    }
    if (tid == 0) out_loss[0] = partial[0] / (float)MM;
}

// ---------------------------------------------------------------------------
extern "C" void kernel_launch(void* const* d_in, const int* in_sizes, int n_in,
                              void* d_out, int out_size) {
    const float* z = (const float*)d_in[0];
    const float* e = (const float*)d_in[1];
    float* out = (float*)d_out;

    cudaFuncSetAttribute(gemm_dist_kernel,
                         cudaFuncAttributeMaxDynamicSharedMemorySize, SMEM_TOTAL);

    init_colmin_kernel<<<(MM + 255) / 256, 256>>>();
    prep_eB_kernel<<<(MM * DD / 4 + 255) / 256, 256>>>(e);
    esq_kernel<<<(MM * 32 + 255) / 256, 256>>>(e);

    gemm_dist_kernel<<<256, 256, SMEM_TOTAL>>>(z, out);

    loss_kernel<<<1, 256>>>(out + (size_t)NN * MM);
}